// round 14
// baseline (speedup 1.0000x reference)
#include <cuda_runtime.h>
#include <cuda_bf16.h>
#include <cuda_fp16.h>
#include <cstdint>

// Problem constants
#define BB 8
#define CC 128
#define HH 128
#define WW 128
#define HWSZ (HH*WW)          // 16384

// Scratch (device globals: allocation-free)
__device__ __half g_offh[(size_t)BB * 2 * CC * HWSZ];   // conv1 out (B,2C,H,W) fp16
__device__ float g_xT   [(size_t)BB * HWSZ * CC];       // x    transposed (B,H,W,C), tf32
__device__ float g_xoffT[(size_t)BB * HWSZ * CC];       // deformed, transposed (B,H,W,C), tf32
__device__ float g_wp1  [(size_t)9 * 256 * 128];        // w_off  packed (t,oc,ic), tf32
__device__ float g_wp2  [(size_t)9 * 128 * 128];        // w_conv packed (t,oc,ic), tf32
__device__ float g_rsum [(size_t)BB * HH * 128];        // per-row BN partial sums
__device__ float g_rsum2[(size_t)BB * HH * 128];        // per-row BN partial sumsq
__device__ float g_scale[CC];
__device__ float g_shift[CC];

__device__ __forceinline__ float tf32r(float v) {
    float r;
    asm("cvt.rna.tf32.f32 %0, %1;" : "=f"(r) : "f"(v));
    return r;
}
__device__ __forceinline__ uint32_t smem_u32(const void* p) {
    uint32_t a;
    asm("{ .reg .u64 t; cvta.to.shared.u64 t, %1; cvt.u32.u64 %0, t; }"
        : "=r"(a) : "l"(p));
    return a;
}
#define CP_ASYNC16(dst, src, sz) \
    asm volatile("cp.async.cg.shared.global [%0], [%1], 16, %2;" \
                 :: "r"(dst), "l"(src), "r"(sz))
#define CP_COMMIT()  asm volatile("cp.async.commit_group;")
#define CP_WAIT0()   asm volatile("cp.async.wait_group 0;")
#define LDSM_X4(r0, r1, r2, r3, addr) \
    asm volatile("ldmatrix.sync.aligned.m8n8.x4.shared.b16 {%0,%1,%2,%3}, [%4];" \
                 : "=r"(r0), "=r"(r1), "=r"(r2), "=r"(r3) : "r"(addr))

// ---------------------------------------------------------------------------
// Implicit-GEMM conv 3x3 via warp-level tf32 mma.sync, HALO B-tiles,
// TWO-ROW CTA tile.
// CTA: 256 threads / 8 warps (2m x 4n); tile 64 oc x 256 px (rows y0,y0+1);
// warp tile 32 oc x 64 px; 2 CTAs/SM.
// K loop: 24 chunks of (dy, 16-ic). Each chunk fills:
//   A: 3 kx-taps x 64 oc x 16 ic           (unchanged vs 1-row tile)
//   B: 2 HALO blocks of 130 px-rows x 16ic (input rows y0+dy-1, y0+dy)
// vs the 1-row tile this HALVES barriers per MMA and cuts fill-bytes/MMA
// ~30%. +-1 px = +-LDA floats on the fragment base (kx taps share one fill).
// LDA=20: ldmatrix conflict-free.
// ---------------------------------------------------------------------------
#define NTHR   256
#define LDA    20
#define ATILE3 (3 * 64 * LDA * 4)           // 15360 B
#define BTILE2 (2 * 130 * LDA * 4)          // 20800 B
#define STAGE  (ATILE3 + BTILE2)            // 36160 B
#define SMEM_TOTAL_CONV (2 * STAGE)         // 72320 B (>= 66560 epilogue)
#define LDT    260                          // epilogue stride (floats, 256 px)

__global__ void __launch_bounds__(NTHR, 2)
conv_mma_kernel(const float* __restrict__ xT,   // (B,H,W,C) tf32
                const float* __restrict__ wp,   // (9,OC,128) tf32
                const float* __restrict__ bias, // (OC,) or nullptr
                float* __restrict__ out,        // (B,OC,H,W) fp32 (or null)
                __half* __restrict__ outh,      // (B,OC,H,W) fp16 (or null)
                int OC, int do_relu, int do_bn)
{
    extern __shared__ char smem[];
    const uint32_t sbase = smem_u32(smem);

    const int tid  = threadIdx.x;
    const int wid  = tid >> 5;
    const int lane = tid & 31;
    const int wm   = wid & 1;                 // warp m (2): 32 oc each
    const int wn   = wid >> 1;                // warp n (4): 64 px each
    const int wrr  = wn >> 1;                 // output row within pair (0/1)
    const int wp0  = (wn & 1) * 64;           // px base within the row

    const int rp  = blockIdx.x;               // row-pair id 0 .. BB*HH/2-1
    const int b   = rp >> 6;
    const int y0  = (rp & 63) << 1;           // rows y0, y0+1
    const int ocb = blockIdx.y << 6;          // 64-oc block

    // ldmatrix per-lane addressing (byte offsets within a tile)
    const int l8   = lane & 7;
    const int tsel = lane >> 3;               // matrix index 0..3
    uint32_t aoff[2];                         // within one tap sub-tile
    #pragma unroll
    for (int mt = 0; mt < 2; mt++)
        aoff[mt] = (uint32_t)(((wm * 32 + mt * 16 + (tsel & 1) * 8 + l8) * LDA
                               + (tsel >> 1) * 4) * 4);
    uint32_t boff[4];                         // halo row (tap adds +tt rows)
    #pragma unroll
    for (int p = 0; p < 4; p++)
        boff[p] = (uint32_t)(((wrr * 130 + wp0 + (2 * p + (tsel >> 1)) * 8 + l8) * LDA
                              + (tsel & 1) * 4) * 4);

    float acc[2][8][4];
    #pragma unroll
    for (int mt = 0; mt < 2; mt++)
        #pragma unroll
        for (int nt = 0; nt < 8; nt++)
            #pragma unroll
            for (int i = 0; i < 4; i++) acc[mt][nt][i] = 0.f;

    // ---- async fill of one chunk (dy, 16-ic block) into stage st
    auto issue_chunk = [&](int kb, int st) {
        const int dy  = kb >> 3;              // 0..2
        const int ic0 = (kb & 7) << 4;        // 0..112
        const uint32_t dA = sbase + (uint32_t)(st * STAGE);
        const uint32_t dB = dA + ATILE3;
        // A: 3 taps x 64 oc x 16 ic = 768 float4 (3 per thread)
        #pragma unroll
        for (int i = 0; i < 3; i++) {
            const int v  = tid + i * NTHR;    // 0..767
            const int tt = v >> 8;            // kx tap 0..2
            const int u  = v & 255;
            const int r  = u >> 2;            // oc 0..63
            const int g  = u & 3;             // ic float4 group 0..3
            const float* src = wp + ((size_t)((dy * 3 + tt) * OC + ocb + r)) * 128
                             + ic0 + g * 4;
            CP_ASYNC16(dA + (uint32_t)(((tt * 64 + r) * LDA + g * 4) * 4), src, 16);
        }
        // B halo: 2 blocks x 130 rows x 16 ic = 1040 float4
        #pragma unroll
        for (int i = 0; i < 5; i++) {
            const int v = tid + i * NTHR;
            if (v < 1040) {
                const int rr = (v >= 520);    // output-row block
                const int u  = v - rr * 520;
                const int r  = u >> 2;        // halo row 0..129
                const int g  = u & 3;
                const int gy = y0 + rr + dy - 1;
                const int gx = r - 1;
                const bool ok = ((unsigned)gy < 128u) && ((unsigned)gx < 128u);
                const float* src = xT + (((size_t)b * 128 + (ok ? gy : 0)) * 128
                                         + (ok ? gx : 0)) * 128 + ic0 + g * 4;
                CP_ASYNC16(dB + (uint32_t)(((rr * 130 + r) * LDA + g * 4) * 4),
                           src, ok ? 16 : 0);
            }
        }
        CP_COMMIT();
    };

    issue_chunk(0, 0);

    for (int kb = 0; kb < 24; kb++) {
        CP_WAIT0();                          // my fills for chunk kb complete
        __syncthreads();                     // all fills visible; all warps
                                             // past compute kb-1
        if (kb < 23) issue_chunk(kb + 1, (kb + 1) & 1);

        const uint32_t sA = sbase + (uint32_t)((kb & 1) * STAGE);
        const uint32_t sB = sA + ATILE3;

        #pragma unroll
        for (int tt = 0; tt < 3; tt++) {     // kx tap: B shift = +tt rows
            const uint32_t aBase = sA + (uint32_t)(tt * 64 * LDA * 4);
            const uint32_t bBase = sB + (uint32_t)(tt * LDA * 4);
            #pragma unroll
            for (int s = 0; s < 2; s++) {
                const uint32_t kbyte = (uint32_t)(s * 32);
                uint32_t af[2][4], bf[8][2];
                #pragma unroll
                for (int mt = 0; mt < 2; mt++)
                    LDSM_X4(af[mt][0], af[mt][1], af[mt][2], af[mt][3],
                            aBase + aoff[mt] + kbyte);
                #pragma unroll
                for (int p = 0; p < 4; p++)
                    LDSM_X4(bf[2*p][0], bf[2*p][1], bf[2*p+1][0], bf[2*p+1][1],
                            bBase + boff[p] + kbyte);
                #pragma unroll
                for (int mt = 0; mt < 2; mt++)
                    #pragma unroll
                    for (int nt = 0; nt < 8; nt++)
                        asm volatile(
                            "mma.sync.aligned.m16n8k8.row.col.f32.tf32.tf32.f32 "
                            "{%0,%1,%2,%3}, {%4,%5,%6,%7}, {%8,%9}, {%0,%1,%2,%3};"
                            : "+f"(acc[mt][nt][0]), "+f"(acc[mt][nt][1]),
                              "+f"(acc[mt][nt][2]), "+f"(acc[mt][nt][3])
                            : "r"(af[mt][0]), "r"(af[mt][1]), "r"(af[mt][2]), "r"(af[mt][3]),
                              "r"(bf[nt][0]), "r"(bf[nt][1]));
            }
        }
    }

    // ---- epilogue: bias + relu into SMEM buffer [oc][256 px], stride LDT
    __syncthreads();
    const int lr = lane >> 2;
    const int lc = lane & 3;
    float* s_t = (float*)smem;
    #pragma unroll
    for (int mt = 0; mt < 2; mt++) {
        const int r0 = wm * 32 + mt * 16 + lr;
        const float bv0 = bias ? bias[ocb + r0]     : 0.f;
        const float bv1 = bias ? bias[ocb + r0 + 8] : 0.f;
        #pragma unroll
        for (int nt = 0; nt < 8; nt++) {
            const int c0 = wn * 64 + nt * 8 + 2 * lc;   // 0..255
            float v0 = acc[mt][nt][0] + bv0;
            float v1 = acc[mt][nt][1] + bv0;
            float v2 = acc[mt][nt][2] + bv1;
            float v3 = acc[mt][nt][3] + bv1;
            if (do_relu) {
                v0 = fmaxf(v0, 0.f); v1 = fmaxf(v1, 0.f);
                v2 = fmaxf(v2, 0.f); v3 = fmaxf(v3, 0.f);
            }
            *(float2*)(s_t + r0 * LDT + c0)       = make_float2(v0, v1);
            *(float2*)(s_t + (r0 + 8) * LDT + c0) = make_float2(v2, v3);
        }
    }
    __syncthreads();

    if (outh) {
        // fp16 output: 64 oc x 256 px; 8 halfs (16B) per store
        for (int idx = tid; idx < 64 * 32; idx += NTHR) {
            const int oc  = idx >> 5;
            const int seg = idx & 31;
            const int py  = y0 + (seg >> 4);
            const int col = (seg & 15) * 8;
            const float* sp = s_t + oc * LDT + (seg >> 4) * 128 + col;
            __half2 h[4];
            #pragma unroll
            for (int k = 0; k < 4; k++)
                h[k] = __floats2half2_rn(sp[2 * k], sp[2 * k + 1]);
            *(uint4*)(outh + ((size_t)b * OC + ocb + oc) * HWSZ + py * WW + col)
                = *(uint4*)h;
        }
    } else {
        for (int idx = tid; idx < 64 * 64; idx += NTHR) {
            const int oc = idx >> 6;
            const int xg = idx & 63;
            const int py = y0 + (xg >> 5);
            const int col = (xg & 31) << 2;
            float4 v = *(float4*)(s_t + oc * LDT + (xg >> 5) * 128 + col);
            *(float4*)(out + ((size_t)b * OC + ocb + oc) * HWSZ + py * WW + col) = v;
        }
    }

    // ---- fused BN partial stats (deterministic; per row x per oc)
    if (do_bn) {
        const int oc = tid >> 2;              // 0..63
        const int rr = (tid >> 1) & 1;        // which output row
        const int h  = tid & 1;               // half of the row
        const float* rpt = s_t + oc * LDT + rr * 128 + h * 64;
        float s = 0.f, s2 = 0.f;
        #pragma unroll 8
        for (int j = 0; j < 64; j++) {
            float v = rpt[j];
            s += v; s2 += v * v;
        }
        s  += __shfl_xor_sync(0xffffffffu, s, 1);
        s2 += __shfl_xor_sync(0xffffffffu, s2, 1);
        if (h == 0) {
            const int rowg = b * 128 + y0 + rr;
            g_rsum [(size_t)rowg * 128 + ocb + oc] = s;
            g_rsum2[(size_t)rowg * 128 + ocb + oc] = s2;
        }
    }
}

// ---------------------------------------------------------------------------
// Transpose (B,C,HW) -> (B,HW,C) with tf32 rounding.
// ---------------------------------------------------------------------------
__global__ void transpose_tf32_kernel(const float* __restrict__ in,
                                      float* __restrict__ outT)
{
    __shared__ float tile[32][33];
    const int b  = blockIdx.z;
    const int c0 = blockIdx.y << 5;
    const int q0 = blockIdx.x << 5;
    const int tx = threadIdx.x;          // 32
    const int ty = threadIdx.y;          // 8
    #pragma unroll
    for (int i = ty; i < 32; i += 8)
        tile[i][tx] = in[((size_t)b * CC + c0 + i) * HWSZ + q0 + tx];
    __syncthreads();
    #pragma unroll
    for (int j = ty; j < 32; j += 8)
        outT[((size_t)b * HWSZ + q0 + j) * CC + c0 + tx] = tf32r(tile[tx][j]);
}

// Pack weights (OC,128,3,3) -> (9,OC,128), tf32-rounded.
__global__ void pack_w_kernel(const float* __restrict__ w,
                              float* __restrict__ wpk, int OC)
{
    const int idx = blockIdx.x * 256 + threadIdx.x;
    if (idx >= OC * 128 * 9) return;
    const int oc = idx / (128 * 9);
    const int r  = idx - oc * (128 * 9);
    const int ic = r / 9;
    const int t  = r - ic * 9;
    wpk[((size_t)t * OC + oc) * 128 + ic] = tf32r(w[idx]);
}

// ---------------------------------------------------------------------------
// Fused deformable bilinear sampling + transpose, fp16 offsets in.
// Writes (B,H,W,C) tf32 directly (quirky-reshape semantics preserved).
// ---------------------------------------------------------------------------
__global__ void deformT_kernel(const float* __restrict__ x,
                               const __half* __restrict__ offh,
                               float* __restrict__ xoT)
{
    __shared__ float tile[32][33];
    const int b  = blockIdx.z;
    const int c0 = blockIdx.y << 5;
    const int q0 = blockIdx.x << 5;
    const int tx = threadIdx.x;
    const int ty = threadIdx.y;

    #pragma unroll
    for (int i = ty; i < 32; i += 8) {
        const int c = c0 + i;
        const int q = q0 + tx;
        const int p = b * CC + c;
        const int pi = q >> 7;
        const int pj = q & 127;

        const __half2 o2h = *(const __half2*)(offh + (size_t)p * 2 * HWSZ + 2 * q);
        const float2 o2 = __half22float2(o2h);
        float yc = fminf(fmaxf(o2.x + (float)pi, 0.f), 127.f);
        float xc = fminf(fmaxf(o2.y + (float)pj, 0.f), 127.f);
        float y0f = floorf(yc), y1f = ceilf(yc);
        float x0f = floorf(xc), x1f = ceilf(xc);
        int y0 = (int)y0f, y1 = (int)y1f;
        int x0 = (int)x0f, x1 = (int)x1f;

        const float* img = x + (size_t)p * HWSZ;
        float v_lt = img[y0 * WW + x0];
        float v_rb = img[y1 * WW + x1];
        float v_lb = img[y0 * WW + x1];
        float v_rt = img[y1 * WW + x0];

        float dy = yc - y0f;
        float dx = xc - x0f;
        float v_t = v_lt + (v_rt - v_lt) * dy;
        float v_b = v_lb + (v_rb - v_lb) * dy;
        tile[i][tx] = tf32r(v_t + (v_b - v_t) * dx);
    }
    __syncthreads();
    #pragma unroll
    for (int j = ty; j < 32; j += 8)
        xoT[((size_t)b * HWSZ + q0 + j) * CC + c0 + tx] = tile[tx][j];
}

// ---------------------------------------------------------------------------
// BN finalize, PARALLEL: one block per channel, 256 threads.
// ---------------------------------------------------------------------------
__global__ void bn_finalize_kernel(const float* __restrict__ gamma,
                                   const float* __restrict__ beta)
{
    const int c = blockIdx.x;
    const int t = threadIdx.x;               // 256 threads
    float s = 0.f, s2 = 0.f;
    #pragma unroll
    for (int i = 0; i < 4; i++) {
        const int r = t + i * 256;           // 0..1023
        s  += g_rsum [(size_t)r * 128 + c];
        s2 += g_rsum2[(size_t)r * 128 + c];
    }
    __shared__ float rs[256], rs2[256];
    rs[t] = s; rs2[t] = s2;
    __syncthreads();
    for (int st = 128; st > 0; st >>= 1) {
        if (t < st) {
            rs[t]  += rs[t + st];
            rs2[t] += rs2[t + st];
        }
        __syncthreads();
    }
    if (t == 0) {
        const float n = (float)(BB * HWSZ);
        float mean = rs[0] / n;
        float var  = rs2[0] / n - mean * mean;
        float sc   = gamma[c] * rsqrtf(var + 1e-5f);
        g_scale[c] = sc;
        g_shift[c] = beta[c] - mean * sc;
    }
}

// float4-vectorized BN apply (4 elements per thread, same channel per quad)
__global__ void bn_apply_kernel(float* __restrict__ ych)
{
    const int gid = blockIdx.x * 256 + threadIdx.x;   // float4 index
    const int c = (gid >> 12) & 127;                  // 4096 quads per channel
    const float sc = g_scale[c];
    const float sh = g_shift[c];
    float4 v = *(float4*)(ych + (size_t)gid * 4);
    v.x = fmaf(v.x, sc, sh);
    v.y = fmaf(v.y, sc, sh);
    v.z = fmaf(v.z, sc, sh);
    v.w = fmaf(v.w, sc, sh);
    *(float4*)(ych + (size_t)gid * 4) = v;
}

// ---------------------------------------------------------------------------
extern "C" void kernel_launch(void* const* d_in, const int* in_sizes, int n_in,
                              void* d_out, int out_size)
{
    const float* x      = (const float*)d_in[0];
    const float* w_off  = (const float*)d_in[1];
    const float* w_conv = (const float*)d_in[2];
    const float* b_conv = (const float*)d_in[3];
    const float* gamma  = (const float*)d_in[4];
    const float* beta   = (const float*)d_in[5];
    float* out = (float*)d_out;

    __half* offh;
    float *xT, *xoffT, *wp1, *wp2;
    cudaGetSymbolAddress((void**)&offh,  g_offh);
    cudaGetSymbolAddress((void**)&xT,    g_xT);
    cudaGetSymbolAddress((void**)&xoffT, g_xoffT);
    cudaGetSymbolAddress((void**)&wp1,   g_wp1);
    cudaGetSymbolAddress((void**)&wp2,   g_wp2);

    cudaFuncSetAttribute(conv_mma_kernel,
                         cudaFuncAttributeMaxDynamicSharedMemorySize, SMEM_TOTAL_CONV);

    // 0) transpose x -> xT (tf32), pack both weight tensors
    dim3 tg(HWSZ / 32, CC / 32, BB), tb(32, 8);
    transpose_tf32_kernel<<<tg, tb>>>(x, xT);
    pack_w_kernel<<<(256 * 128 * 9 + 255) / 256, 256>>>(w_off, wp1, 256);
    pack_w_kernel<<<(128 * 128 * 9 + 255) / 256, 256>>>(w_conv, wp2, 128);

    // 1) offsets = conv3x3(x, w_off), OC=256, fp16 output
    dim3 g1(BB * HH / 2, 4);
    conv_mma_kernel<<<g1, NTHR, SMEM_TOTAL_CONV>>>(xT, wp1, nullptr,
                                                   nullptr, offh, 256, 0, 0);

    // 2) fused deformable sampling + transpose -> xoffT (tf32)
    deformT_kernel<<<tg, tb>>>(x, offh, xoffT);

    // 3) y = relu(conv3x3(x_off, w_conv) + b_conv) + fused BN partials
    dim3 g2(BB * HH / 2, 2);
    conv_mma_kernel<<<g2, NTHR, SMEM_TOTAL_CONV>>>(xoffT, wp2, b_conv,
                                                   out, nullptr, 128, 1, 1);

    // 4) batchnorm finalize (parallel) + apply in-place on d_out
    const int nelem = BB * CC * HWSZ;
    bn_finalize_kernel<<<CC, 256>>>(gamma, beta);
    bn_apply_kernel<<<nelem / 4 / 256, 256>>>(out);
}

// round 15
// speedup vs baseline: 1.0499x; 1.0499x over previous
#include <cuda_runtime.h>
#include <cuda_bf16.h>
#include <cuda_fp16.h>
#include <cstdint>

// Problem constants
#define BB 8
#define CC 128
#define HH 128
#define WW 128
#define HWSZ (HH*WW)          // 16384

// Scratch (device globals: allocation-free)
__device__ __half g_offh[(size_t)BB * 2 * CC * HWSZ];   // conv1 out (B,2C,H,W) fp16
__device__ float g_xT   [(size_t)BB * HWSZ * CC];       // x    transposed (B,H,W,C), tf32
__device__ float g_xoffT[(size_t)BB * HWSZ * CC];       // deformed, transposed (B,H,W,C), tf32
__device__ float g_wp1  [(size_t)9 * 256 * 128];        // w_off  packed (t,oc,ic), tf32
__device__ float g_wp2  [(size_t)9 * 128 * 128];        // w_conv packed (t,oc,ic), tf32
__device__ float g_rsum [(size_t)BB * HH * 128];        // per-row BN partial sums
__device__ float g_rsum2[(size_t)BB * HH * 128];        // per-row BN partial sumsq
__device__ float g_scale[CC];
__device__ float g_shift[CC];

__device__ __forceinline__ float tf32r(float v) {
    float r;
    asm("cvt.rna.tf32.f32 %0, %1;" : "=f"(r) : "f"(v));
    return r;
}
__device__ __forceinline__ uint32_t smem_u32(const void* p) {
    uint32_t a;
    asm("{ .reg .u64 t; cvta.to.shared.u64 t, %1; cvt.u32.u64 %0, t; }"
        : "=r"(a) : "l"(p));
    return a;
}
#define CP_ASYNC16(dst, src, sz) \
    asm volatile("cp.async.cg.shared.global [%0], [%1], 16, %2;" \
                 :: "r"(dst), "l"(src), "r"(sz))
#define CP_COMMIT()  asm volatile("cp.async.commit_group;")
#define CP_WAIT0()   asm volatile("cp.async.wait_group 0;")
#define LDSM_X4(r0, r1, r2, r3, addr) \
    asm volatile("ldmatrix.sync.aligned.m8n8.x4.shared.b16 {%0,%1,%2,%3}, [%4];" \
                 : "=r"(r0), "=r"(r1), "=r"(r2), "=r"(r3) : "r"(addr))

// ---------------------------------------------------------------------------
// Implicit-GEMM conv 3x3 via warp-level tf32 mma.sync, HALO B-tiles.
// (Byte-identical compute structure to the round-13 kernel: 383 us conv1,
// tensor 66.4% — the empirical optimum of this design family. Round-12's
// smaller chunks and round-14's two-row tiles both regressed.)
// CTA: 128 threads / 4 warps (2m x 2n); tile 64 oc x 128 px (one image row);
// warp tile 32 oc x 64 px; 4 CTAs/SM (4 independent barrier domains).
// K loop: 24 chunks of (dy, 16-ic). Each chunk fills:
//   A: 3 kx-taps x 64 oc x 16 ic   (tap-major sub-tiles)
//   B: HALO 130 px-rows x 16 ic    (px -1..128 of input row y+dy-1)
// All 3 kx taps compute from ONE B fill (+-1 px shift = +-LDA floats on the
// fragment base). LDA=20: conflict-free ldmatrix.
// 2-stage cp.async pipeline, ONE __syncthreads per chunk.
// ---------------------------------------------------------------------------
#define NTHR   128
#define LDA    20
#define ATILE3 (3 * 64 * LDA * 4)           // 15360 B (3 tap sub-tiles)
#define BTILE  (130 * LDA * 4)              // 10400 B (halo)
#define STAGE  (ATILE3 + BTILE)             // 25760 B
#define SMEM_TOTAL_CONV (2 * STAGE)         // 51520 B  (>= 33792 epilogue)
#define LDT    132                          // epilogue transpose stride (floats)

__global__ void __launch_bounds__(NTHR, 4)
conv_mma_kernel(const float* __restrict__ xT,   // (B,H,W,C) tf32
                const float* __restrict__ wp,   // (9,OC,128) tf32
                const float* __restrict__ bias, // (OC,) or nullptr
                float* __restrict__ out,        // (B,OC,H,W) fp32 (or null)
                __half* __restrict__ outh,      // (B,OC,H,W) fp16 (or null)
                int OC, int do_relu, int do_bn)
{
    extern __shared__ char smem[];
    const uint32_t sbase = smem_u32(smem);

    const int tid  = threadIdx.x;
    const int wid  = tid >> 5;
    const int lane = tid & 31;
    const int wm   = wid & 1;                 // warp m (2): 32 oc each
    const int wn   = wid >> 1;                // warp n (2): 64 px each

    const int row = blockIdx.x;               // 0 .. BB*HH-1
    const int b   = row >> 7;
    const int y   = row & 127;
    const int ocb = blockIdx.y << 6;          // 64-oc block

    // ldmatrix per-lane addressing (byte offsets within a tile)
    const int l8   = lane & 7;
    const int tsel = lane >> 3;               // matrix index 0..3
    uint32_t aoff[2];                         // within one tap sub-tile
    #pragma unroll
    for (int mt = 0; mt < 2; mt++)
        aoff[mt] = (uint32_t)(((wm * 32 + mt * 16 + (tsel & 1) * 8 + l8) * LDA
                               + (tsel >> 1) * 4) * 4);
    uint32_t boff[4];                         // halo row = px (tap adds +t rows)
    #pragma unroll
    for (int p = 0; p < 4; p++)
        boff[p] = (uint32_t)(((wn * 64 + (2 * p + (tsel >> 1)) * 8 + l8) * LDA
                              + (tsel & 1) * 4) * 4);

    float acc[2][8][4];
    #pragma unroll
    for (int mt = 0; mt < 2; mt++)
        #pragma unroll
        for (int nt = 0; nt < 8; nt++)
            #pragma unroll
            for (int i = 0; i < 4; i++) acc[mt][nt][i] = 0.f;

    // ---- async fill of one chunk (dy, 16-ic block) into stage st
    auto issue_chunk = [&](int kb, int st) {
        const int dy  = kb >> 3;              // 0..2
        const int ic0 = (kb & 7) << 4;        // 0..112
        const uint32_t dA = sbase + (uint32_t)(st * STAGE);
        const uint32_t dB = dA + ATILE3;
        // A: 3 taps x 64 oc x 16 ic = 768 float4 (6 per thread)
        #pragma unroll
        for (int i = 0; i < 6; i++) {
            const int v  = tid + i * NTHR;    // 0..767
            const int tt = v >> 8;            // kx tap 0..2
            const int u  = v & 255;
            const int r  = u >> 2;            // oc 0..63
            const int g  = u & 3;             // ic float4 group 0..3
            const float* src = wp + ((size_t)((dy * 3 + tt) * OC + ocb + r)) * 128
                             + ic0 + g * 4;
            CP_ASYNC16(dA + (uint32_t)(((tt * 64 + r) * LDA + g * 4) * 4), src, 16);
        }
        // B halo: 130 rows (px -1..128) x 16 ic = 520 float4
        const int gy = y + dy - 1;
        const bool oky = ((unsigned)gy < 128u);
        #pragma unroll
        for (int i = 0; i < 5; i++) {
            const int v = tid + i * NTHR;
            if (v < 520) {
                const int r  = v >> 2;        // halo row 0..129
                const int g  = v & 3;
                const int gx = r - 1;
                const bool ok = oky && ((unsigned)gx < 128u);
                const float* src = xT + (((size_t)b * 128 + (ok ? gy : 0)) * 128
                                         + (ok ? gx : 0)) * 128 + ic0 + g * 4;
                CP_ASYNC16(dB + (uint32_t)((r * LDA + g * 4) * 4), src, ok ? 16 : 0);
            }
        }
        CP_COMMIT();
    };

    issue_chunk(0, 0);

    for (int kb = 0; kb < 24; kb++) {
        CP_WAIT0();                          // my fills for chunk kb complete
        __syncthreads();                     // all fills visible; all warps
                                             // past compute kb-1
        if (kb < 23) issue_chunk(kb + 1, (kb + 1) & 1);

        const uint32_t sA = sbase + (uint32_t)((kb & 1) * STAGE);
        const uint32_t sB = sA + ATILE3;

        #pragma unroll
        for (int tt = 0; tt < 3; tt++) {     // kx tap: B shift = +tt rows
            const uint32_t aBase = sA + (uint32_t)(tt * 64 * LDA * 4);
            const uint32_t bBase = sB + (uint32_t)(tt * LDA * 4);
            #pragma unroll
            for (int s = 0; s < 2; s++) {
                const uint32_t kbyte = (uint32_t)(s * 32);
                uint32_t af[2][4], bf[8][2];
                #pragma unroll
                for (int mt = 0; mt < 2; mt++)
                    LDSM_X4(af[mt][0], af[mt][1], af[mt][2], af[mt][3],
                            aBase + aoff[mt] + kbyte);
                #pragma unroll
                for (int p = 0; p < 4; p++)
                    LDSM_X4(bf[2*p][0], bf[2*p][1], bf[2*p+1][0], bf[2*p+1][1],
                            bBase + boff[p] + kbyte);
                #pragma unroll
                for (int mt = 0; mt < 2; mt++)
                    #pragma unroll
                    for (int nt = 0; nt < 8; nt++)
                        asm volatile(
                            "mma.sync.aligned.m16n8k8.row.col.f32.tf32.tf32.f32 "
                            "{%0,%1,%2,%3}, {%4,%5,%6,%7}, {%8,%9}, {%0,%1,%2,%3};"
                            : "+f"(acc[mt][nt][0]), "+f"(acc[mt][nt][1]),
                              "+f"(acc[mt][nt][2]), "+f"(acc[mt][nt][3])
                            : "r"(af[mt][0]), "r"(af[mt][1]), "r"(af[mt][2]), "r"(af[mt][3]),
                              "r"(bf[nt][0]), "r"(bf[nt][1]));
            }
        }
    }

    // ---- epilogue: bias + relu into SMEM transpose buffer, coalesced store
    __syncthreads();
    const int lr = lane >> 2;
    const int lc = lane & 3;
    float* s_t = (float*)smem;                // [oc][px], stride LDT (64 rows)
    #pragma unroll
    for (int mt = 0; mt < 2; mt++) {
        const int r0 = wm * 32 + mt * 16 + lr;
        const float bv0 = bias ? bias[ocb + r0]     : 0.f;
        const float bv1 = bias ? bias[ocb + r0 + 8] : 0.f;
        #pragma unroll
        for (int nt = 0; nt < 8; nt++) {
            const int c0 = wn * 64 + nt * 8 + 2 * lc;
            float v0 = acc[mt][nt][0] + bv0;
            float v1 = acc[mt][nt][1] + bv0;
            float v2 = acc[mt][nt][2] + bv1;
            float v3 = acc[mt][nt][3] + bv1;
            if (do_relu) {
                v0 = fmaxf(v0, 0.f); v1 = fmaxf(v1, 0.f);
                v2 = fmaxf(v2, 0.f); v3 = fmaxf(v3, 0.f);
            }
            *(float2*)(s_t + r0 * LDT + c0)       = make_float2(v0, v1);
            *(float2*)(s_t + (r0 + 8) * LDT + c0) = make_float2(v2, v3);
        }
    }
    __syncthreads();

    if (outh) {
        // fp16 output path (offsets): 64 oc x 128 px, 8 halfs (16B) per store
        for (int idx = tid; idx < 64 * 16; idx += NTHR) {
            const int oc  = idx >> 4;
            const int seg = idx & 15;
            const float* sp = s_t + oc * LDT + seg * 8;
            __half2 h[4];
            #pragma unroll
            for (int k = 0; k < 4; k++)
                h[k] = __floats2half2_rn(sp[2 * k], sp[2 * k + 1]);
            *(uint4*)(outh + ((size_t)b * OC + ocb + oc) * HWSZ + y * WW + seg * 8)
                = *(uint4*)h;
        }
    } else {
        for (int idx = tid; idx < 64 * 32; idx += NTHR) {
            const int oc = idx >> 5;
            const int xg = idx & 31;
            float4 v = *(float4*)(s_t + oc * LDT + xg * 4);
            *(float4*)(out + ((size_t)b * OC + ocb + oc) * HWSZ + y * WW + xg * 4) = v;
        }
    }

    // ---- fused BN partial stats (deterministic; per row x per oc)
    if (do_bn) {
        const int oc = tid >> 1;              // 0..63
        const int h  = tid & 1;               // half of the row
        const float* rp = s_t + oc * LDT + h * 64;
        float s = 0.f, s2 = 0.f;
        #pragma unroll 8
        for (int j = 0; j < 64; j++) {
            float v = rp[j];
            s += v; s2 += v * v;
        }
        s  += __shfl_xor_sync(0xffffffffu, s, 1);
        s2 += __shfl_xor_sync(0xffffffffu, s2, 1);
        if (h == 0) {
            g_rsum [(size_t)row * 128 + ocb + oc] = s;
            g_rsum2[(size_t)row * 128 + ocb + oc] = s2;
        }
    }
}

// ---------------------------------------------------------------------------
// Transpose (B,C,HW) -> (B,HW,C) with tf32 rounding.
// ---------------------------------------------------------------------------
__global__ void transpose_tf32_kernel(const float* __restrict__ in,
                                      float* __restrict__ outT)
{
    __shared__ float tile[32][33];
    const int b  = blockIdx.z;
    const int c0 = blockIdx.y << 5;
    const int q0 = blockIdx.x << 5;
    const int tx = threadIdx.x;          // 32
    const int ty = threadIdx.y;          // 8
    #pragma unroll
    for (int i = ty; i < 32; i += 8)
        tile[i][tx] = in[((size_t)b * CC + c0 + i) * HWSZ + q0 + tx];
    __syncthreads();
    #pragma unroll
    for (int j = ty; j < 32; j += 8)
        outT[((size_t)b * HWSZ + q0 + j) * CC + c0 + tx] = tf32r(tile[tx][j]);
}

// Pack BOTH weight tensors (OC,128,3,3) -> (9,OC,128), tf32-rounded, in one
// launch: indices [0, 256*128*9) -> wp1, [256*128*9, +128*128*9) -> wp2.
__global__ void pack_w_both_kernel(const float* __restrict__ w1,
                                   const float* __restrict__ w2,
                                   float* __restrict__ wpk1,
                                   float* __restrict__ wpk2)
{
    const int N1 = 256 * 128 * 9;
    const int N2 = 128 * 128 * 9;
    int idx = blockIdx.x * 256 + threadIdx.x;
    const float* w; float* wpk; int OC;
    if (idx < N1) { w = w1; wpk = wpk1; OC = 256; }
    else if (idx < N1 + N2) { idx -= N1; w = w2; wpk = wpk2; OC = 128; }
    else return;
    const int oc = idx / (128 * 9);
    const int r  = idx - oc * (128 * 9);
    const int ic = r / 9;
    const int t  = r - ic * 9;
    wpk[((size_t)t * OC + oc) * 128 + ic] = tf32r(w[idx]);
}

// ---------------------------------------------------------------------------
// Fused deformable bilinear sampling + transpose, fp16 offsets in.
// Writes (B,H,W,C) tf32 directly (quirky-reshape semantics preserved).
// ---------------------------------------------------------------------------
__global__ void deformT_kernel(const float* __restrict__ x,
                               const __half* __restrict__ offh,
                               float* __restrict__ xoT)
{
    __shared__ float tile[32][33];
    const int b  = blockIdx.z;
    const int c0 = blockIdx.y << 5;
    const int q0 = blockIdx.x << 5;
    const int tx = threadIdx.x;
    const int ty = threadIdx.y;

    #pragma unroll
    for (int i = ty; i < 32; i += 8) {
        const int c = c0 + i;
        const int q = q0 + tx;
        const int p = b * CC + c;
        const int pi = q >> 7;
        const int pj = q & 127;

        const __half2 o2h = *(const __half2*)(offh + (size_t)p * 2 * HWSZ + 2 * q);
        const float2 o2 = __half22float2(o2h);
        float yc = fminf(fmaxf(o2.x + (float)pi, 0.f), 127.f);
        float xc = fminf(fmaxf(o2.y + (float)pj, 0.f), 127.f);
        float y0f = floorf(yc), y1f = ceilf(yc);
        float x0f = floorf(xc), x1f = ceilf(xc);
        int y0 = (int)y0f, y1 = (int)y1f;
        int x0 = (int)x0f, x1 = (int)x1f;

        const float* img = x + (size_t)p * HWSZ;
        float v_lt = img[y0 * WW + x0];
        float v_rb = img[y1 * WW + x1];
        float v_lb = img[y0 * WW + x1];
        float v_rt = img[y1 * WW + x0];

        float dy = yc - y0f;
        float dx = xc - x0f;
        float v_t = v_lt + (v_rt - v_lt) * dy;
        float v_b = v_lb + (v_rb - v_lb) * dy;
        tile[i][tx] = tf32r(v_t + (v_b - v_t) * dx);
    }
    __syncthreads();
    #pragma unroll
    for (int j = ty; j < 32; j += 8)
        xoT[((size_t)b * HWSZ + q0 + j) * CC + c0 + tx] = tile[tx][j];
}

// ---------------------------------------------------------------------------
// BN finalize, PARALLEL: one block per channel, 256 threads.
// ---------------------------------------------------------------------------
__global__ void bn_finalize_kernel(const float* __restrict__ gamma,
                                   const float* __restrict__ beta)
{
    const int c = blockIdx.x;
    const int t = threadIdx.x;               // 256 threads
    float s = 0.f, s2 = 0.f;
    #pragma unroll
    for (int i = 0; i < 4; i++) {
        const int r = t + i * 256;           // 0..1023
        s  += g_rsum [(size_t)r * 128 + c];
        s2 += g_rsum2[(size_t)r * 128 + c];
    }
    __shared__ float rs[256], rs2[256];
    rs[t] = s; rs2[t] = s2;
    __syncthreads();
    for (int st = 128; st > 0; st >>= 1) {
        if (t < st) {
            rs[t]  += rs[t + st];
            rs2[t] += rs2[t + st];
        }
        __syncthreads();
    }
    if (t == 0) {
        const float n = (float)(BB * HWSZ);
        float mean = rs[0] / n;
        float var  = rs2[0] / n - mean * mean;
        float sc   = gamma[c] * rsqrtf(var + 1e-5f);
        g_scale[c] = sc;
        g_shift[c] = beta[c] - mean * sc;
    }
}

// BN apply: 2x float4 per thread (same channel within each 8-float span).
__global__ void bn_apply_kernel(float* __restrict__ ych)
{
    const int gid = blockIdx.x * 256 + threadIdx.x;   // 8-float group index
    const int c = (gid >> 11) & 127;                  // 2048 groups per channel
    const float sc = g_scale[c];
    const float sh = g_shift[c];
    float4* p = (float4*)(ych + (size_t)gid * 8);
    float4 v0 = p[0], v1 = p[1];
    v0.x = fmaf(v0.x, sc, sh); v0.y = fmaf(v0.y, sc, sh);
    v0.z = fmaf(v0.z, sc, sh); v0.w = fmaf(v0.w, sc, sh);
    v1.x = fmaf(v1.x, sc, sh); v1.y = fmaf(v1.y, sc, sh);
    v1.z = fmaf(v1.z, sc, sh); v1.w = fmaf(v1.w, sc, sh);
    p[0] = v0; p[1] = v1;
}

// ---------------------------------------------------------------------------
extern "C" void kernel_launch(void* const* d_in, const int* in_sizes, int n_in,
                              void* d_out, int out_size)
{
    const float* x      = (const float*)d_in[0];
    const float* w_off  = (const float*)d_in[1];
    const float* w_conv = (const float*)d_in[2];
    const float* b_conv = (const float*)d_in[3];
    const float* gamma  = (const float*)d_in[4];
    const float* beta   = (const float*)d_in[5];
    float* out = (float*)d_out;

    __half* offh;
    float *xT, *xoffT, *wp1, *wp2;
    cudaGetSymbolAddress((void**)&offh,  g_offh);
    cudaGetSymbolAddress((void**)&xT,    g_xT);
    cudaGetSymbolAddress((void**)&xoffT, g_xoffT);
    cudaGetSymbolAddress((void**)&wp1,   g_wp1);
    cudaGetSymbolAddress((void**)&wp2,   g_wp2);

    cudaFuncSetAttribute(conv_mma_kernel,
                         cudaFuncAttributeMaxDynamicSharedMemorySize, SMEM_TOTAL_CONV);

    // 0) transpose x -> xT (tf32), pack both weight tensors (one launch)
    dim3 tg(HWSZ / 32, CC / 32, BB), tb(32, 8);
    transpose_tf32_kernel<<<tg, tb>>>(x, xT);
    const int npack = (256 + 128) * 128 * 9;
    pack_w_both_kernel<<<(npack + 255) / 256, 256>>>(w_off, w_conv, wp1, wp2);

    // 1) offsets = conv3x3(x, w_off), OC=256, fp16 output
    dim3 g1(BB * HH, 4);
    conv_mma_kernel<<<g1, NTHR, SMEM_TOTAL_CONV>>>(xT, wp1, nullptr,
                                                   nullptr, offh, 256, 0, 0);

    // 2) fused deformable sampling + transpose -> xoffT (tf32)
    deformT_kernel<<<tg, tb>>>(x, offh, xoffT);

    // 3) y = relu(conv3x3(x_off, w_conv) + b_conv) + fused BN partials
    dim3 g2(BB * HH, 2);
    conv_mma_kernel<<<g2, NTHR, SMEM_TOTAL_CONV>>>(xoffT, wp2, b_conv,
                                                   out, nullptr, 128, 1, 1);

    // 4) batchnorm finalize (parallel) + apply in-place on d_out
    const int nelem = BB * CC * HWSZ;
    bn_finalize_kernel<<<CC, 256>>>(gamma, beta);
    bn_apply_kernel<<<nelem / 8 / 256, 256>>>(out);
}

// round 16
// speedup vs baseline: 1.0865x; 1.0348x over previous
#include <cuda_runtime.h>
#include <cuda_bf16.h>
#include <cuda_fp16.h>
#include <cstdint>

// Problem constants
#define BB 8
#define CC 128
#define HH 128
#define WW 128
#define HWSZ (HH*WW)          // 16384

// Scratch (device globals: allocation-free)
__device__ __half g_offh[(size_t)BB * 2 * CC * HWSZ];   // conv1 out (B,2C,H,W) fp16
__device__ float g_xT   [(size_t)BB * HWSZ * CC];       // x    transposed (B,H,W,C), tf32
__device__ float g_xoffT[(size_t)BB * HWSZ * CC];       // deformed, transposed (B,H,W,C), tf32
__device__ float g_wp1  [(size_t)9 * 256 * 128];        // w_off  packed (t,oc,ic), tf32
__device__ float g_wp2  [(size_t)9 * 128 * 128];        // w_conv packed (t,oc,ic), tf32
__device__ float g_rsum [(size_t)BB * HH * 128];        // per-row BN partial sums
__device__ float g_rsum2[(size_t)BB * HH * 128];        // per-row BN partial sumsq
__device__ float g_scale[CC];
__device__ float g_shift[CC];

__device__ __forceinline__ float tf32r(float v) {
    float r;
    asm("cvt.rna.tf32.f32 %0, %1;" : "=f"(r) : "f"(v));
    return r;
}
__device__ __forceinline__ uint32_t smem_u32(const void* p) {
    uint32_t a;
    asm("{ .reg .u64 t; cvta.to.shared.u64 t, %1; cvt.u32.u64 %0, t; }"
        : "=r"(a) : "l"(p));
    return a;
}
#define CP_ASYNC16(dst, src, sz) \
    asm volatile("cp.async.cg.shared.global [%0], [%1], 16, %2;" \
                 :: "r"(dst), "l"(src), "r"(sz))
#define CP_COMMIT()  asm volatile("cp.async.commit_group;")
#define CP_WAIT0()   asm volatile("cp.async.wait_group 0;")
#define LDSM_X4(r0, r1, r2, r3, addr) \
    asm volatile("ldmatrix.sync.aligned.m8n8.x4.shared.b16 {%0,%1,%2,%3}, [%4];" \
                 : "=r"(r0), "=r"(r1), "=r"(r2), "=r"(r3) : "r"(addr))

// ---------------------------------------------------------------------------
// Implicit-GEMM conv 3x3 via warp-level tf32 mma.sync, HALO B-tiles.
// (Byte-identical compute structure to the round-13 kernel: 383 us conv1,
// tensor 66.4% — the empirical optimum of this design family.)
// CTA: 128 threads / 4 warps (2m x 2n); tile 64 oc x 128 px (one image row);
// warp tile 32 oc x 64 px; 4 CTAs/SM (4 independent barrier domains).
// K loop: 24 chunks of (dy, 16-ic); A: 3 kx-taps x 64 oc x 16 ic;
// B: HALO 130 px-rows x 16 ic; all 3 kx taps share one B fill
// (+-1 px = +-LDA floats on the fragment base). LDA=20: conflict-free.
// 2-stage cp.async pipeline, ONE __syncthreads per chunk.
// ---------------------------------------------------------------------------
#define NTHR   128
#define LDA    20
#define ATILE3 (3 * 64 * LDA * 4)           // 15360 B (3 tap sub-tiles)
#define BTILE  (130 * LDA * 4)              // 10400 B (halo)
#define STAGE  (ATILE3 + BTILE)             // 25760 B
#define SMEM_TOTAL_CONV (2 * STAGE)         // 51520 B  (>= 33792 epilogue)
#define LDT    132                          // epilogue transpose stride (floats)

__global__ void __launch_bounds__(NTHR, 4)
conv_mma_kernel(const float* __restrict__ xT,   // (B,H,W,C) tf32
                const float* __restrict__ wp,   // (9,OC,128) tf32
                const float* __restrict__ bias, // (OC,) or nullptr
                float* __restrict__ out,        // (B,OC,H,W) fp32 (or null)
                __half* __restrict__ outh,      // (B,OC,H,W) fp16 (or null)
                int OC, int do_relu, int do_bn)
{
    extern __shared__ char smem[];
    const uint32_t sbase = smem_u32(smem);

    const int tid  = threadIdx.x;
    const int wid  = tid >> 5;
    const int lane = tid & 31;
    const int wm   = wid & 1;                 // warp m (2): 32 oc each
    const int wn   = wid >> 1;                // warp n (2): 64 px each

    const int row = blockIdx.x;               // 0 .. BB*HH-1
    const int b   = row >> 7;
    const int y   = row & 127;
    const int ocb = blockIdx.y << 6;          // 64-oc block

    // ldmatrix per-lane addressing (byte offsets within a tile)
    const int l8   = lane & 7;
    const int tsel = lane >> 3;               // matrix index 0..3
    uint32_t aoff[2];                         // within one tap sub-tile
    #pragma unroll
    for (int mt = 0; mt < 2; mt++)
        aoff[mt] = (uint32_t)(((wm * 32 + mt * 16 + (tsel & 1) * 8 + l8) * LDA
                               + (tsel >> 1) * 4) * 4);
    uint32_t boff[4];                         // halo row = px (tap adds +t rows)
    #pragma unroll
    for (int p = 0; p < 4; p++)
        boff[p] = (uint32_t)(((wn * 64 + (2 * p + (tsel >> 1)) * 8 + l8) * LDA
                              + (tsel & 1) * 4) * 4);

    float acc[2][8][4];
    #pragma unroll
    for (int mt = 0; mt < 2; mt++)
        #pragma unroll
        for (int nt = 0; nt < 8; nt++)
            #pragma unroll
            for (int i = 0; i < 4; i++) acc[mt][nt][i] = 0.f;

    // ---- async fill of one chunk (dy, 16-ic block) into stage st
    auto issue_chunk = [&](int kb, int st) {
        const int dy  = kb >> 3;              // 0..2
        const int ic0 = (kb & 7) << 4;        // 0..112
        const uint32_t dA = sbase + (uint32_t)(st * STAGE);
        const uint32_t dB = dA + ATILE3;
        // A: 3 taps x 64 oc x 16 ic = 768 float4 (6 per thread)
        #pragma unroll
        for (int i = 0; i < 6; i++) {
            const int v  = tid + i * NTHR;    // 0..767
            const int tt = v >> 8;            // kx tap 0..2
            const int u  = v & 255;
            const int r  = u >> 2;            // oc 0..63
            const int g  = u & 3;             // ic float4 group 0..3
            const float* src = wp + ((size_t)((dy * 3 + tt) * OC + ocb + r)) * 128
                             + ic0 + g * 4;
            CP_ASYNC16(dA + (uint32_t)(((tt * 64 + r) * LDA + g * 4) * 4), src, 16);
        }
        // B halo: 130 rows (px -1..128) x 16 ic = 520 float4
        const int gy = y + dy - 1;
        const bool oky = ((unsigned)gy < 128u);
        #pragma unroll
        for (int i = 0; i < 5; i++) {
            const int v = tid + i * NTHR;
            if (v < 520) {
                const int r  = v >> 2;        // halo row 0..129
                const int g  = v & 3;
                const int gx = r - 1;
                const bool ok = oky && ((unsigned)gx < 128u);
                const float* src = xT + (((size_t)b * 128 + (ok ? gy : 0)) * 128
                                         + (ok ? gx : 0)) * 128 + ic0 + g * 4;
                CP_ASYNC16(dB + (uint32_t)((r * LDA + g * 4) * 4), src, ok ? 16 : 0);
            }
        }
        CP_COMMIT();
    };

    issue_chunk(0, 0);

    for (int kb = 0; kb < 24; kb++) {
        CP_WAIT0();                          // my fills for chunk kb complete
        __syncthreads();                     // all fills visible; all warps
                                             // past compute kb-1
        if (kb < 23) issue_chunk(kb + 1, (kb + 1) & 1);

        const uint32_t sA = sbase + (uint32_t)((kb & 1) * STAGE);
        const uint32_t sB = sA + ATILE3;

        #pragma unroll
        for (int tt = 0; tt < 3; tt++) {     // kx tap: B shift = +tt rows
            const uint32_t aBase = sA + (uint32_t)(tt * 64 * LDA * 4);
            const uint32_t bBase = sB + (uint32_t)(tt * LDA * 4);
            #pragma unroll
            for (int s = 0; s < 2; s++) {
                const uint32_t kbyte = (uint32_t)(s * 32);
                uint32_t af[2][4], bf[8][2];
                #pragma unroll
                for (int mt = 0; mt < 2; mt++)
                    LDSM_X4(af[mt][0], af[mt][1], af[mt][2], af[mt][3],
                            aBase + aoff[mt] + kbyte);
                #pragma unroll
                for (int p = 0; p < 4; p++)
                    LDSM_X4(bf[2*p][0], bf[2*p][1], bf[2*p+1][0], bf[2*p+1][1],
                            bBase + boff[p] + kbyte);
                #pragma unroll
                for (int mt = 0; mt < 2; mt++)
                    #pragma unroll
                    for (int nt = 0; nt < 8; nt++)
                        asm volatile(
                            "mma.sync.aligned.m16n8k8.row.col.f32.tf32.tf32.f32 "
                            "{%0,%1,%2,%3}, {%4,%5,%6,%7}, {%8,%9}, {%0,%1,%2,%3};"
                            : "+f"(acc[mt][nt][0]), "+f"(acc[mt][nt][1]),
                              "+f"(acc[mt][nt][2]), "+f"(acc[mt][nt][3])
                            : "r"(af[mt][0]), "r"(af[mt][1]), "r"(af[mt][2]), "r"(af[mt][3]),
                              "r"(bf[nt][0]), "r"(bf[nt][1]));
            }
        }
    }

    // ---- epilogue: bias + relu into SMEM transpose buffer, coalesced store
    __syncthreads();
    const int lr = lane >> 2;
    const int lc = lane & 3;
    float* s_t = (float*)smem;                // [oc][px], stride LDT (64 rows)
    #pragma unroll
    for (int mt = 0; mt < 2; mt++) {
        const int r0 = wm * 32 + mt * 16 + lr;
        const float bv0 = bias ? bias[ocb + r0]     : 0.f;
        const float bv1 = bias ? bias[ocb + r0 + 8] : 0.f;
        #pragma unroll
        for (int nt = 0; nt < 8; nt++) {
            const int c0 = wn * 64 + nt * 8 + 2 * lc;
            float v0 = acc[mt][nt][0] + bv0;
            float v1 = acc[mt][nt][1] + bv0;
            float v2 = acc[mt][nt][2] + bv1;
            float v3 = acc[mt][nt][3] + bv1;
            if (do_relu) {
                v0 = fmaxf(v0, 0.f); v1 = fmaxf(v1, 0.f);
                v2 = fmaxf(v2, 0.f); v3 = fmaxf(v3, 0.f);
            }
            *(float2*)(s_t + r0 * LDT + c0)       = make_float2(v0, v1);
            *(float2*)(s_t + (r0 + 8) * LDT + c0) = make_float2(v2, v3);
        }
    }
    __syncthreads();

    if (outh) {
        // fp16 output path (offsets): 64 oc x 128 px, 8 halfs (16B) per store
        for (int idx = tid; idx < 64 * 16; idx += NTHR) {
            const int oc  = idx >> 4;
            const int seg = idx & 15;
            const float* sp = s_t + oc * LDT + seg * 8;
            __half2 h[4];
            #pragma unroll
            for (int k = 0; k < 4; k++)
                h[k] = __floats2half2_rn(sp[2 * k], sp[2 * k + 1]);
            *(uint4*)(outh + ((size_t)b * OC + ocb + oc) * HWSZ + y * WW + seg * 8)
                = *(uint4*)h;
        }
    } else {
        for (int idx = tid; idx < 64 * 32; idx += NTHR) {
            const int oc = idx >> 5;
            const int xg = idx & 31;
            float4 v = *(float4*)(s_t + oc * LDT + xg * 4);
            *(float4*)(out + ((size_t)b * OC + ocb + oc) * HWSZ + y * WW + xg * 4) = v;
        }
    }

    // ---- fused BN partial stats (deterministic; per row x per oc)
    if (do_bn) {
        const int oc = tid >> 1;              // 0..63
        const int h  = tid & 1;               // half of the row
        const float* rp = s_t + oc * LDT + h * 64;
        float s = 0.f, s2 = 0.f;
        #pragma unroll 8
        for (int j = 0; j < 64; j++) {
            float v = rp[j];
            s += v; s2 += v * v;
        }
        s  += __shfl_xor_sync(0xffffffffu, s, 1);
        s2 += __shfl_xor_sync(0xffffffffu, s2, 1);
        if (h == 0) {
            g_rsum [(size_t)row * 128 + ocb + oc] = s;
            g_rsum2[(size_t)row * 128 + ocb + oc] = s2;
        }
    }
}

// ---------------------------------------------------------------------------
// Transpose (B,C,HW) -> (B,HW,C) with tf32 rounding.
// ---------------------------------------------------------------------------
__global__ void transpose_tf32_kernel(const float* __restrict__ in,
                                      float* __restrict__ outT)
{
    __shared__ float tile[32][33];
    const int b  = blockIdx.z;
    const int c0 = blockIdx.y << 5;
    const int q0 = blockIdx.x << 5;
    const int tx = threadIdx.x;          // 32
    const int ty = threadIdx.y;          // 8
    #pragma unroll
    for (int i = ty; i < 32; i += 8)
        tile[i][tx] = in[((size_t)b * CC + c0 + i) * HWSZ + q0 + tx];
    __syncthreads();
    #pragma unroll
    for (int j = ty; j < 32; j += 8)
        outT[((size_t)b * HWSZ + q0 + j) * CC + c0 + tx] = tf32r(tile[tx][j]);
}

// Pack BOTH weight tensors (OC,128,3,3) -> (9,OC,128), tf32-rounded.
__global__ void pack_w_both_kernel(const float* __restrict__ w1,
                                   const float* __restrict__ w2,
                                   float* __restrict__ wpk1,
                                   float* __restrict__ wpk2)
{
    const int N1 = 256 * 128 * 9;
    const int N2 = 128 * 128 * 9;
    int idx = blockIdx.x * 256 + threadIdx.x;
    const float* w; float* wpk; int OC;
    if (idx < N1) { w = w1; wpk = wpk1; OC = 256; }
    else if (idx < N1 + N2) { idx -= N1; w = w2; wpk = wpk2; OC = 128; }
    else return;
    const int oc = idx / (128 * 9);
    const int r  = idx - oc * (128 * 9);
    const int ic = r / 9;
    const int t  = r - ic * 9;
    wpk[((size_t)t * OC + oc) * 128 + ic] = tf32r(w[idx]);
}

// ---------------------------------------------------------------------------
// Fused deformable bilinear sampling + transpose, LSU-optimized:
// block (32,8) handles 32 channels x 128 pixels (= one image row).
// Each thread processes 4 consecutive pixels: ONE uint4 load fetches the 4
// half2 offset pairs, results stored as ONE float4 STS. Offset-load and STS
// instruction counts drop 4x; 16 independent gathers in flight per thread.
// ceil replaced by floor + (frac>0) (bit-identical for clamped coords).
// ---------------------------------------------------------------------------
__global__ void deformT_kernel(const float* __restrict__ x,
                               const __half* __restrict__ offh,
                               float* __restrict__ xoT)
{
    __shared__ float tile[32][132];      // row = channel; 132*4 % 16 == 0
    const int b  = blockIdx.z;
    const int c0 = blockIdx.y << 5;
    const int qb = blockIdx.x << 7;      // 128-pixel block = one image row
    const int tx = threadIdx.x;          // 32: 4-pixel group
    const int ty = threadIdx.y;          // 8: channel stride
    const int i  = blockIdx.x & 127;     // image row (qb >> 7 within image)
    const int j0 = tx << 2;

    #pragma unroll
    for (int cc = ty; cc < 32; cc += 8) {
        const int c = c0 + cc;
        const int p = b * CC + c;
        const uint4 ov = *(const uint4*)(offh + (size_t)p * 2 * HWSZ + 2 * (qb + j0));
        const __half2* oh = (const __half2*)&ov;
        const float* img = x + (size_t)p * HWSZ;
        float res[4];
        #pragma unroll
        for (int k = 0; k < 4; k++) {
            const float2 o2 = __half22float2(oh[k]);
            const int j = j0 + k;
            float yc = fminf(fmaxf(o2.x + (float)i, 0.f), 127.f);
            float xc = fminf(fmaxf(o2.y + (float)j, 0.f), 127.f);
            float y0f = floorf(yc), x0f = floorf(xc);
            int y0 = (int)y0f, x0 = (int)x0f;
            float dy = yc - y0f, dx = xc - x0f;
            int y1 = y0 + (dy > 0.f ? 1 : 0);
            int x1 = x0 + (dx > 0.f ? 1 : 0);
            float v_lt = img[y0 * WW + x0];
            float v_rb = img[y1 * WW + x1];
            float v_lb = img[y0 * WW + x1];
            float v_rt = img[y1 * WW + x0];
            float v_t = v_lt + (v_rt - v_lt) * dy;
            float v_b = v_lb + (v_rb - v_lb) * dy;
            res[k] = tf32r(v_t + (v_b - v_t) * dx);
        }
        *(float4*)&tile[cc][j0] = *(float4*)res;
    }
    __syncthreads();

    // write phase: lanes over channel (coalesced 128B), loop over pixels
    #pragma unroll
    for (int k = 0; k < 16; k++) {
        const int q = ty * 16 + k;
        xoT[((size_t)b * HWSZ + qb + q) * CC + c0 + tx] = tile[tx][q];
    }
}

// ---------------------------------------------------------------------------
// BN finalize, PARALLEL: one block per channel, 256 threads.
// ---------------------------------------------------------------------------
__global__ void bn_finalize_kernel(const float* __restrict__ gamma,
                                   const float* __restrict__ beta)
{
    const int c = blockIdx.x;
    const int t = threadIdx.x;               // 256 threads
    float s = 0.f, s2 = 0.f;
    #pragma unroll
    for (int i = 0; i < 4; i++) {
        const int r = t + i * 256;           // 0..1023
        s  += g_rsum [(size_t)r * 128 + c];
        s2 += g_rsum2[(size_t)r * 128 + c];
    }
    __shared__ float rs[256], rs2[256];
    rs[t] = s; rs2[t] = s2;
    __syncthreads();
    for (int st = 128; st > 0; st >>= 1) {
        if (t < st) {
            rs[t]  += rs[t + st];
            rs2[t] += rs2[t + st];
        }
        __syncthreads();
    }
    if (t == 0) {
        const float n = (float)(BB * HWSZ);
        float mean = rs[0] / n;
        float var  = rs2[0] / n - mean * mean;
        float sc   = gamma[c] * rsqrtf(var + 1e-5f);
        g_scale[c] = sc;
        g_shift[c] = beta[c] - mean * sc;
    }
}

// float4-vectorized BN apply (R13 form)
__global__ void bn_apply_kernel(float* __restrict__ ych)
{
    const int gid = blockIdx.x * 256 + threadIdx.x;   // float4 index
    const int c = (gid >> 12) & 127;                  // 4096 quads per channel
    const float sc = g_scale[c];
    const float sh = g_shift[c];
    float4 v = *(float4*)(ych + (size_t)gid * 4);
    v.x = fmaf(v.x, sc, sh);
    v.y = fmaf(v.y, sc, sh);
    v.z = fmaf(v.z, sc, sh);
    v.w = fmaf(v.w, sc, sh);
    *(float4*)(ych + (size_t)gid * 4) = v;
}

// ---------------------------------------------------------------------------
extern "C" void kernel_launch(void* const* d_in, const int* in_sizes, int n_in,
                              void* d_out, int out_size)
{
    const float* x      = (const float*)d_in[0];
    const float* w_off  = (const float*)d_in[1];
    const float* w_conv = (const float*)d_in[2];
    const float* b_conv = (const float*)d_in[3];
    const float* gamma  = (const float*)d_in[4];
    const float* beta   = (const float*)d_in[5];
    float* out = (float*)d_out;

    __half* offh;
    float *xT, *xoffT, *wp1, *wp2;
    cudaGetSymbolAddress((void**)&offh,  g_offh);
    cudaGetSymbolAddress((void**)&xT,    g_xT);
    cudaGetSymbolAddress((void**)&xoffT, g_xoffT);
    cudaGetSymbolAddress((void**)&wp1,   g_wp1);
    cudaGetSymbolAddress((void**)&wp2,   g_wp2);

    cudaFuncSetAttribute(conv_mma_kernel,
                         cudaFuncAttributeMaxDynamicSharedMemorySize, SMEM_TOTAL_CONV);

    // 0) transpose x -> xT (tf32), pack both weight tensors (one launch)
    dim3 tg(HWSZ / 32, CC / 32, BB), tb(32, 8);
    transpose_tf32_kernel<<<tg, tb>>>(x, xT);
    const int npack = (256 + 128) * 128 * 9;
    pack_w_both_kernel<<<(npack + 255) / 256, 256>>>(w_off, w_conv, wp1, wp2);

    // 1) offsets = conv3x3(x, w_off), OC=256, fp16 output
    dim3 g1(BB * HH, 4);
    conv_mma_kernel<<<g1, NTHR, SMEM_TOTAL_CONV>>>(xT, wp1, nullptr,
                                                   nullptr, offh, 256, 0, 0);

    // 2) fused deformable sampling + transpose -> xoffT (tf32)
    dim3 dg(HWSZ / 128, CC / 32, BB), db(32, 8);
    deformT_kernel<<<dg, db>>>(x, offh, xoffT);

    // 3) y = relu(conv3x3(x_off, w_conv) + b_conv) + fused BN partials
    dim3 g2(BB * HH, 2);
    conv_mma_kernel<<<g2, NTHR, SMEM_TOTAL_CONV>>>(xoffT, wp2, b_conv,
                                                   out, nullptr, 128, 1, 1);

    // 4) batchnorm finalize (parallel) + apply in-place on d_out
    const int nelem = BB * CC * HWSZ;
    bn_finalize_kernel<<<CC, 256>>>(gamma, beta);
    bn_apply_kernel<<<nelem / 4 / 256, 256>>>(out);
}